// round 15
// baseline (speedup 1.0000x reference)
#include <cuda_runtime.h>
#include <cuda_bf16.h>
#include <cstdint>

#define N_NODES 50000
#define FEAT 128
#define NRELS 4
#define EMAXCAP 262144

// Scratch (static __device__ — no allocation allowed)
__device__ int g_deg[NRELS][N_NODES];          // per-relation in-degree
__device__ int g_off[NRELS][N_NODES];          // CSR exclusive offsets
__device__ int g_cur[NRELS][N_NODES];          // fill cursors
__device__ int g_esrc[NRELS][EMAXCAP];         // CSR edge source ids
// A pre-split to bf16 big/small; +64 rows padding so GEMM tile overruns stay in-bounds
__device__ unsigned short g_Ab[((size_t)NRELS * N_NODES + 64) * FEAT];
__device__ unsigned short g_As[((size_t)NRELS * N_NODES + 64) * FEAT];
__device__ unsigned short g_Wb[NRELS * FEAT * FEAT];   // composed W^T [r][n][k], bf16 big
__device__ unsigned short g_Ws[NRELS * FEAT * FEAT];   // composed W^T [r][n][k], bf16 small

// ---------------------------------------------------------------------------
// helpers
// ---------------------------------------------------------------------------
__device__ __forceinline__ uint32_t smem_u32(const void* p) {
    uint32_t a;
    asm("{ .reg .u64 t; cvta.to.shared.u64 t, %1; cvt.u32.u64 %0, t; }" : "=r"(a) : "l"(p));
    return a;
}
__device__ __forceinline__ unsigned short f2bf(float x) {
    return __bfloat16_as_ushort(__float2bfloat16_rn(x));
}
__device__ __forceinline__ float bf2f(unsigned short u) {
    return __uint_as_float(((uint32_t)u) << 16);
}
__device__ __forceinline__ void ldsm4(uint32_t* r, uint32_t addr) {
    asm volatile("ldmatrix.sync.aligned.m8n8.x4.shared.b16 {%0,%1,%2,%3}, [%4];"
                 : "=r"(r[0]), "=r"(r[1]), "=r"(r[2]), "=r"(r[3]) : "r"(addr));
}
__device__ __forceinline__ void mma_bf16(float* d, const uint32_t* a, uint32_t b0, uint32_t b1) {
    asm volatile(
        "mma.sync.aligned.m16n8k16.row.col.f32.bf16.bf16.f32 "
        "{%0,%1,%2,%3}, {%4,%5,%6,%7}, {%8,%9}, {%0,%1,%2,%3};"
        : "+f"(d[0]), "+f"(d[1]), "+f"(d[2]), "+f"(d[3])
        : "r"(a[0]), "r"(a[1]), "r"(a[2]), "r"(a[3]), "r"(b0), "r"(b1));
}
__device__ __forceinline__ void cp_async16(uint32_t smem_dst, const void* gsrc) {
    asm volatile("cp.async.cg.shared.global [%0], [%1], 16;"
                 :: "r"(smem_dst), "l"(gsrc) : "memory");
}
#define SWZ(off) ((off) ^ (((off) >> 3) & 0x70))

// ---------------------------------------------------------------------------
// W precompute: W^T[r][n][k] composed from bases, split to bf16 big + small
// ---------------------------------------------------------------------------
__global__ void compute_w_kernel(const float* __restrict__ weight,
                                 const float* __restrict__ w_comp) {
    int idx = blockIdx.x * blockDim.x + threadIdx.x;   // 4 * 16384
    int r = idx >> 14;
    int k = idx & 127;
    int n = (idx >> 7) & 127;
    float w = w_comp[r * 2 + 0] * weight[k * 128 + n]
            + w_comp[r * 2 + 1] * weight[16384 + k * 128 + n];
    unsigned short big = f2bf(w);
    g_Wb[idx] = big;
    g_Ws[idx] = f2bf(w - bf2f(big));
}

// ---------------------------------------------------------------------------
// CSR build: count -> scan -> fill (proven in R10)
// ---------------------------------------------------------------------------
__global__ void count_kernel(const int* __restrict__ d0, const int* __restrict__ d1,
                             const int* __restrict__ d2, const int* __restrict__ d3,
                             int E0, int E1, int E2, int E3) {
    int rel = blockIdx.y;
    int e = blockIdx.x * 256 + threadIdx.x;
    const int* dp = (rel == 0) ? d0 : (rel == 1) ? d1 : (rel == 2) ? d2 : d3;
    int E = (rel == 0) ? E0 : (rel == 1) ? E1 : (rel == 2) ? E2 : E3;
    if (e < E) {
        int d = __ldg(dp + e);
        if (d >= 0 && d < N_NODES) atomicAdd(&g_deg[rel][d], 1);
    }
}

__global__ void __launch_bounds__(1024)
scan_kernel() {
    int rel = blockIdx.x;
    __shared__ int sums[1024];
    int tid = threadIdx.x;
    const int CH = 49;                       // 49*1024 = 50176 >= 50000
    int bs = tid * CH;
    int s = 0;
    for (int i = 0; i < CH; i++) {
        int idx = bs + i;
        if (idx < N_NODES) s += g_deg[rel][idx];
    }
    sums[tid] = s;
    __syncthreads();
    for (int d = 1; d < 1024; d <<= 1) {     // Hillis-Steele inclusive scan
        int v = (tid >= d) ? sums[tid - d] : 0;
        __syncthreads();
        sums[tid] += v;
        __syncthreads();
    }
    int run = (tid == 0) ? 0 : sums[tid - 1];
    for (int i = 0; i < CH; i++) {
        int idx = bs + i;
        if (idx < N_NODES) {
            g_off[rel][idx] = run;
            g_cur[rel][idx] = run;
            run += g_deg[rel][idx];
        }
    }
}

__global__ void fill_kernel(const int* __restrict__ s0, const int* __restrict__ d0,
                            const int* __restrict__ s1, const int* __restrict__ d1,
                            const int* __restrict__ s2, const int* __restrict__ d2,
                            const int* __restrict__ s3, const int* __restrict__ d3,
                            int E0, int E1, int E2, int E3) {
    int rel = blockIdx.y;
    int e = blockIdx.x * 256 + threadIdx.x;
    const int* sp = (rel == 0) ? s0 : (rel == 1) ? s1 : (rel == 2) ? s2 : s3;
    const int* dp = (rel == 0) ? d0 : (rel == 1) ? d1 : (rel == 2) ? d2 : d3;
    int E = (rel == 0) ? E0 : (rel == 1) ? E1 : (rel == 2) ? E2 : E3;
    if (e < E) {
        int d = __ldg(dp + e);
        if (d >= 0 && d < N_NODES) {
            int slot = atomicAdd(&g_cur[rel][d], 1);
            if (slot >= 0 && slot < EMAXCAP) g_esrc[rel][slot] = __ldg(sp + e);
        }
    }
}

// ---------------------------------------------------------------------------
// Aggregation: warp per (rel,node) row (200k warps — full TLP, unlike the
// failed in-GEMM version). Gather x rows via CSR (MLP-4 batches), fp32
// register sum, split to bf16 big/small, plain stores (no atomics, and
// deg-0 rows write zeros so no memset of A is needed at all).
// Relation chosen per block (rel = bid & 3) for x-table locality.
// ---------------------------------------------------------------------------
__global__ void __launch_bounds__(256)
aggregate_kernel(const float* __restrict__ x0, const float* __restrict__ x1) {
    int rel = blockIdx.x & 3;
    int node = (blockIdx.x >> 2) * 8 + (threadIdx.x >> 5);
    int lane = threadIdx.x & 31;
    if (node >= N_NODES) return;
    const float* x = (rel < 2) ? x0 : x1;

    int eb = __ldg(&g_off[rel][node]);
    int dg = __ldg(&g_deg[rel][node]);
    const int* ep = &g_esrc[rel][eb];

    float4 a = make_float4(0.f, 0.f, 0.f, 0.f);
    for (int e = 0; e < dg; e += 4) {
        int m = dg - e; if (m > 4) m = 4;
        int srcs[4]; float4 v[4];
        #pragma unroll
        for (int q = 0; q < 4; q++)
            if (q < m) srcs[q] = __ldg(ep + e + q);
        #pragma unroll
        for (int q = 0; q < 4; q++)
            if (q < m) v[q] = __ldg(reinterpret_cast<const float4*>(x + (size_t)srcs[q] * FEAT) + lane);
        #pragma unroll
        for (int q = 0; q < 4; q++)
            if (q < m) { a.x += v[q].x; a.y += v[q].y; a.z += v[q].z; a.w += v[q].w; }
    }

    unsigned short b0 = f2bf(a.x), b1 = f2bf(a.y), b2 = f2bf(a.z), b3 = f2bf(a.w);
    unsigned short s0 = f2bf(a.x - bf2f(b0)), s1 = f2bf(a.y - bf2f(b1));
    unsigned short s2 = f2bf(a.z - bf2f(b2)), s3 = f2bf(a.w - bf2f(b3));
    uint2 Bp = make_uint2(((uint32_t)b1 << 16) | b0, ((uint32_t)b3 << 16) | b2);
    uint2 Sp = make_uint2(((uint32_t)s1 << 16) | s0, ((uint32_t)s3 << 16) | s2);
    size_t off = ((size_t)rel * N_NODES + node) * FEAT + lane * 4;
    *reinterpret_cast<uint2*>(g_Ab + off) = Bp;
    *reinterpret_cast<uint2*>(g_As + off) = Sp;
}

// ---------------------------------------------------------------------------
// bf16 mma.sync GEMM with big/small compensation (3 products).
// CTA tile M=64 x N=128, 4 chunks (2 rels x 2 kchunks of 64). A is now
// pre-split bf16 in global, so BOTH A and B stage via cp.async with
// double buffers (A 2x16KB + B 2x32KB = 96KB -> occ 2). Chunk c+1's loads
// are issued before chunk c's MMAs (wait_group 1) — no exposed staging.
// 8 warps as 2(M) x 4(N); warp tile 32x32.
// ---------------------------------------------------------------------------
#define SM_A0 0                  // Ab @ +0 (8K), As @ +8192
#define SM_A1 16384
#define SM_B0 32768              // Bb @ +0 (16K), Bs @ +16384
#define SM_B1 65536
#define SMEM_BYTES 98304

__global__ void __launch_bounds__(256, 2)
gemm_kernel(const float* __restrict__ bias, float* __restrict__ out) {
    extern __shared__ char smem_raw[];
    const uint32_t base = smem_u32(smem_raw);

    const int t = blockIdx.y;
    const int row0 = blockIdx.x * 64;
    const int tid = threadIdx.x;
    const int lane = tid & 31;
    const int warp = tid >> 5;
    const int m0 = (warp & 1) * 32;      // warp row offset in 64-row tile
    const int n0 = (warp >> 1) * 32;     // warp col offset in 128-col tile

    float acc[2][4][4];
    #pragma unroll
    for (int mf = 0; mf < 2; mf++)
        #pragma unroll
        for (int nf = 0; nf < 4; nf++)
            #pragma unroll
            for (int i = 0; i < 4; i++) acc[mf][nf][i] = 0.f;

    // ldmatrix lane addressing (8x8 tile rows), hoisted
    const int lrow = (lane & 7) + 8 * ((lane >> 3) & 1);
    const int lkb  = (lane >> 4) * 8;

    // A staging coordinates (j = 0,1): 512 16B-groups over 256 threads
    int arow[2], akq[2];
    #pragma unroll
    for (int j = 0; j < 2; j++) {
        int i = tid + j * 256;
        arow[j] = i >> 3;                // 0..63
        akq[j] = i & 7;
    }
    // B staging coordinates (j = 0..3): 1024 16B-groups over 256 threads
    int bn[4], bkq[4];
    #pragma unroll
    for (int j = 0; j < 4; j++) {
        int i = tid + j * 256;
        bn[j] = i >> 3;                  // 0..127
        bkq[j] = i & 7;
    }

    // stage chunk c into buffer (c&1): one commit group = A(big,small) + B(big,small)
    auto issue_chunk = [&](int c) {
        const int rel = t + (c >> 1) * 2;
        const int kbase = (c & 1) * 64;
        const uint32_t abuf = (c & 1) ? (base + SM_A1) : (base + SM_A0);
        const uint32_t bbuf = (c & 1) ? (base + SM_B1) : (base + SM_B0);
        const unsigned short* Ab = g_Ab + ((size_t)rel * N_NODES + row0) * FEAT + kbase;
        const unsigned short* As = g_As + ((size_t)rel * N_NODES + row0) * FEAT + kbase;
        #pragma unroll
        for (int j = 0; j < 2; j++) {
            uint32_t sw = SWZ((uint32_t)(arow[j] * 128 + akq[j] * 16));
            size_t go = (size_t)arow[j] * FEAT + akq[j] * 8;
            cp_async16(abuf + sw, Ab + go);
            cp_async16(abuf + 8192 + sw, As + go);
        }
        const unsigned short* WBb = g_Wb + rel * FEAT * FEAT + kbase;
        const unsigned short* WSb = g_Ws + rel * FEAT * FEAT + kbase;
        #pragma unroll
        for (int j = 0; j < 4; j++) {
            uint32_t sw = SWZ((uint32_t)(bn[j] * 128 + bkq[j] * 16));
            size_t go = (size_t)bn[j] * FEAT + bkq[j] * 8;
            cp_async16(bbuf + sw, WBb + go);
            cp_async16(bbuf + 16384 + sw, WSb + go);
        }
        asm volatile("cp.async.commit_group;" ::: "memory");
    };

    issue_chunk(0);

    #pragma unroll 1
    for (int c = 0; c < 4; c++) {
        const uint32_t abuf = (c & 1) ? (base + SM_A1) : (base + SM_A0);
        const uint32_t bbuf = (c & 1) ? (base + SM_B1) : (base + SM_B0);

        if (c) __syncthreads();          // MMA(c-1) done before buffer (c+1)&1 refill
        if (c < 3) issue_chunk(c + 1);
        if (c < 3) {
            asm volatile("cp.async.wait_group 1;" ::: "memory");   // chunk c landed
        } else {
            asm volatile("cp.async.wait_group 0;" ::: "memory");
        }
        __syncthreads();

        // ---- compute: 4 k16 steps ----
        #pragma unroll
        for (int ks = 0; ks < 4; ks++) {
            const int kk0 = ks * 16;

            uint32_t aB[2][4], aS[2][4];
            #pragma unroll
            for (int mf = 0; mf < 2; mf++) {
                uint32_t sw = SWZ((uint32_t)((m0 + mf * 16 + lrow) * 128 + (kk0 + lkb) * 2));
                ldsm4(aB[mf], abuf + sw);
                ldsm4(aS[mf], abuf + 8192 + sw);
            }
            uint32_t bB[2][4], bS[2][4];
            #pragma unroll
            for (int ng = 0; ng < 2; ng++) {
                uint32_t sw = SWZ((uint32_t)((n0 + ng * 16 + lrow) * 128 + (kk0 + lkb) * 2));
                ldsm4(bB[ng], bbuf + sw);
                ldsm4(bS[ng], bbuf + 16384 + sw);
            }
            #pragma unroll
            for (int mf = 0; mf < 2; mf++) {
                #pragma unroll
                for (int nf = 0; nf < 4; nf++) {
                    int ng = nf >> 1, sel = nf & 1;
                    mma_bf16(acc[mf][nf], aB[mf], bB[ng][sel], bB[ng][sel + 2]);
                    mma_bf16(acc[mf][nf], aB[mf], bS[ng][sel], bS[ng][sel + 2]);
                    mma_bf16(acc[mf][nf], aS[mf], bB[ng][sel], bB[ng][sel + 2]);
                }
            }
        }
    }

    // ---- epilogue: + bias, store fp32 ----
    #pragma unroll
    for (int nf = 0; nf < 4; nf++) {
        int col = n0 + nf * 8 + 2 * (lane & 3);
        float bx = __ldg(bias + col);
        float by = __ldg(bias + col + 1);
        #pragma unroll
        for (int mf = 0; mf < 2; mf++) {
            int g = row0 + m0 + mf * 16 + (lane >> 2);
            const float* a4 = acc[mf][nf];
            if (g < N_NODES) {
                float2 o = make_float2(a4[0] + bx, a4[1] + by);
                *reinterpret_cast<float2*>(out + ((size_t)t * N_NODES + g) * FEAT + col) = o;
            }
            if (g + 8 < N_NODES) {
                float2 o = make_float2(a4[2] + bx, a4[3] + by);
                *reinterpret_cast<float2*>(out + ((size_t)t * N_NODES + g + 8) * FEAT + col) = o;
            }
        }
    }
}

// ---------------------------------------------------------------------------
extern "C" void kernel_launch(void* const* d_in, const int* in_sizes, int n_in,
                              void* d_out, int out_size) {
    const float* x0     = (const float*)d_in[0];
    const float* x1     = (const float*)d_in[1];
    const float* weight = (const float*)d_in[2];
    const float* w_comp = (const float*)d_in[3];
    const float* bias   = (const float*)d_in[4];
    const int* src0 = (const int*)d_in[5];  const int* dst0 = (const int*)d_in[6];
    const int* src1 = (const int*)d_in[7];  const int* dst1 = (const int*)d_in[8];
    const int* src2 = (const int*)d_in[9];  const int* dst2 = (const int*)d_in[10];
    const int* src3 = (const int*)d_in[11]; const int* dst3 = (const int*)d_in[12];
    float* out = (float*)d_out;

    void* degptr = nullptr;
    cudaGetSymbolAddress(&degptr, g_deg);
    cudaMemsetAsync(degptr, 0, sizeof(int) * NRELS * N_NODES, 0);   // 800 KB, ~0.2us

    compute_w_kernel<<<256, 256>>>(weight, w_comp);

    int E0 = in_sizes[5], E1 = in_sizes[7], E2 = in_sizes[9], E3 = in_sizes[11];
    int Emax = E0;
    if (E1 > Emax) Emax = E1;
    if (E2 > Emax) Emax = E2;
    if (E3 > Emax) Emax = E3;
    dim3 egrid((unsigned)((Emax + 255) / 256), 4);
    count_kernel<<<egrid, 256>>>(dst0, dst1, dst2, dst3, E0, E1, E2, E3);
    scan_kernel<<<4, 1024>>>();
    fill_kernel<<<egrid, 256>>>(src0, dst0, src1, dst1, src2, dst2, src3, dst3,
                                E0, E1, E2, E3);

    int ablocks = ((N_NODES + 7) / 8) * 4;   // 8 rows per block, rel = bid & 3
    aggregate_kernel<<<ablocks, 256>>>(x0, x1);

    cudaFuncSetAttribute(gemm_kernel, cudaFuncAttributeMaxDynamicSharedMemorySize, SMEM_BYTES);
    gemm_kernel<<<dim3((N_NODES + 63) / 64, 2), 256, SMEM_BYTES>>>(bias, out);
}